// round 7
// baseline (speedup 1.0000x reference)
#include <cuda_runtime.h>
#include <cuda_fp16.h>
#include <cstdint>

#define NB_CAT  8192
#define RANK    16
#define N_COLS  4
#define GRID_CTAS (148 * 6)   // exactly 6 CTAs/SM (launch_bounds) -> all resident

// R7: single fused kernel.
//  Phase 1: convert covar_factor fp32 -> fp16 table (halves L2 sector traffic,
//           doubles L1-resident fraction; R5-proven win).
//  Device-wide sense barrier (all 888 CTAs resident by construction).
//  Phase 2: gather (R6 MLP structure: full 8-load batch + index prefetch),
//           math in half2 (HMUL2+HFMA2 per column, fp32 cross-column accum)
//           to cut issue-pipe pressure that was stealing LDG slots.

__device__ __half2  g_cfh[N_COLS * NB_CAT * RANK / 2];   // 4 MB, layout = cf
__device__ unsigned g_bar_count = 0;
__device__ unsigned g_bar_gen   = 0;

__global__ __launch_bounds__(256, 6) void fused_pair_cov_kernel(
    const int*   __restrict__ x,
    const int*   __restrict__ y,
    const float* __restrict__ cf,     // [N_COLS, NB_CAT, RANK] fp32
    const float* __restrict__ stdv,   // [N_COLS, NB_CAT]
    float*       __restrict__ out,
    int n_pairs)
{
    // ---------------- Phase 1: table conversion ----------------
    {
        const int tid = blockIdx.x * blockDim.x + threadIdx.x;
        const int nth = gridDim.x * blockDim.x;
        const int nh2 = N_COLS * NB_CAT * RANK / 2;   // 1,048,576 half2
        for (int i = tid; i < nh2; i += nth) {
            const float2 v = __ldcg((const float2*)cf + i);
            g_cfh[i] = __float22half2_rn(v);
        }
    }
    __threadfence();          // make table writes visible GPU-wide
    __syncthreads();

    // ---------------- Device-wide barrier (sense/generation) ----------------
    if (threadIdx.x == 0) {
        const unsigned gen = atomicAdd(&g_bar_gen, 0u);   // read BEFORE arriving
        if (atomicAdd(&g_bar_count, 1u) == gridDim.x - 1u) {
            g_bar_count = 0u;                              // reset for next launch
            __threadfence();
            atomicAdd(&g_bar_gen, 1u);                     // release
        } else {
            while (atomicAdd(&g_bar_gen, 0u) == gen) __nanosleep(64);
        }
    }
    __syncthreads();

    // ---------------- Phase 2: pair gather ----------------
    const int lane = threadIdx.x & 31;
    const int sub  = lane & 3;        // 8B chunk of the 32B fp16 row
    const int unit = lane >> 2;       // pair slot (0..7) within warp-iter

    const int warp_global = (int)((blockIdx.x * blockDim.x + threadIdx.x) >> 5);
    const int nwarps      = (int)((gridDim.x * blockDim.x) >> 5);

    const uint2* cfh = (const uint2*)g_cfh;   // row r -> cfh[r*4 + sub]

    int base = warp_global * 8;
    if (base >= n_pairs) return;   // (never taken at this grid/n_pairs)

    // Prime index pipeline
    int4 xi = __ldcg((const int4*)x + base + unit);
    int4 yi = __ldcg((const int4*)y + base + unit);

    while (base < n_pairs) {
        const int nbase = base + nwarps * 8;

        // Issue all 8 row gathers back-to-back (MLP = 8)
        uint2 av[N_COLS], bv[N_COLS];
        av[0] = cfh[(size_t)(0 * NB_CAT + xi.x) * 4 + sub];
        bv[0] = cfh[(size_t)(0 * NB_CAT + yi.x) * 4 + sub];
        av[1] = cfh[(size_t)(1 * NB_CAT + xi.y) * 4 + sub];
        bv[1] = cfh[(size_t)(1 * NB_CAT + yi.y) * 4 + sub];
        av[2] = cfh[(size_t)(2 * NB_CAT + xi.z) * 4 + sub];
        bv[2] = cfh[(size_t)(2 * NB_CAT + yi.z) * 4 + sub];
        av[3] = cfh[(size_t)(3 * NB_CAT + xi.w) * 4 + sub];
        bv[3] = cfh[(size_t)(3 * NB_CAT + yi.w) * 4 + sub];

        // Prefetch next iteration's indices (hide DRAM latency)
        int4 nxi, nyi;
        if (nbase < n_pairs) {
            nxi = __ldcg((const int4*)x + nbase + unit);
            nyi = __ldcg((const int4*)y + nbase + unit);
        }

        // Diagonal term (fp32 std, exact): lane `sub` owns column `sub`
        float acc = 0.0f;
        {
            const int xd = (sub == 0) ? xi.x : (sub == 1) ? xi.y : (sub == 2) ? xi.z : xi.w;
            const int yd = (sub == 0) ? yi.x : (sub == 1) ? yi.y : (sub == 2) ? yi.z : yi.w;
            if (xd == yd) {
                const float s = stdv[sub * NB_CAT + xd];
                acc = s * s;
            }
        }

        // Per-column dot in half2 (1 HMUL2 + 1 HFMA2), fp32 cross-column accum.
        #pragma unroll
        for (int c = 0; c < N_COLS; c++) {
            __half2 p = __hmul2(*(const __half2*)&av[c].x, *(const __half2*)&bv[c].x);
            p = __hfma2(*(const __half2*)&av[c].y, *(const __half2*)&bv[c].y, p);
            const float2 pf = __half22float2(p);
            acc += pf.x;
            acc += pf.y;
        }

        // Reduce over the 4 chunk lanes; lane 0 of each unit writes
        acc += __shfl_xor_sync(0xffffffffu, acc, 1);
        acc += __shfl_xor_sync(0xffffffffu, acc, 2);

        if (sub == 0) {
            out[base + unit] = acc;   // 8 lanes -> 32 contiguous bytes -> 1 wf
        }

        xi = nxi;
        yi = nyi;
        base = nbase;
    }
}

extern "C" void kernel_launch(void* const* d_in, const int* in_sizes, int n_in,
                              void* d_out, int out_size)
{
    const int*   x    = (const int*)d_in[0];
    const int*   y    = (const int*)d_in[1];
    const float* cf   = (const float*)d_in[2];
    const float* stdv = (const float*)d_in[3];
    float*       out  = (float*)d_out;

    const int n_pairs = out_size;  // 1048576

    fused_pair_cov_kernel<<<GRID_CTAS, 256>>>(x, y, cf, stdv, out, n_pairs);
}

// round 8
// speedup vs baseline: 1.1302x; 1.1302x over previous
#include <cuda_runtime.h>
#include <cuda_fp16.h>
#include <cstdint>

#define NB_CAT  8192
#define RANK    16
#define N_COLS  4

// R8: two-kernel structure restored (R7's fused barrier was a 25us loss).
// Gather kernel = R6's MLP machinery (8-load batch + index prefetch)
//               + R7's half2 math (HMUL2+HFMA2 per column, ~2.5x fewer
//                 math-issue slots than the fp32 convert storm)
//               + occupancy 7 (56 warps/SM; half2 frees regs vs R6's 40).

__device__ __half2 g_cfh[N_COLS * NB_CAT * RANK / 2];   // 4 MB, layout = cf

__global__ __launch_bounds__(256) void convert_cf_kernel(const float* __restrict__ cf)
{
    const int i = blockIdx.x * blockDim.x + threadIdx.x;   // half2 index
    const int n = N_COLS * NB_CAT * RANK / 2;              // 1,048,576
    if (i < n) {
        const float2 v = __ldcg((const float2*)cf + i);
        g_cfh[i] = __float22half2_rn(v);
    }
}

__global__ __launch_bounds__(256, 7) void pair_cov_kernel(
    const int*   __restrict__ x,
    const int*   __restrict__ y,
    const float* __restrict__ stdv,   // [N_COLS, NB_CAT]
    float*       __restrict__ out,
    int n_pairs)
{
    const int lane = threadIdx.x & 31;
    const int sub  = lane & 3;        // 8B chunk of the 32B fp16 row
    const int unit = lane >> 2;       // pair slot (0..7) within warp-iter

    const int warp_global = (int)((blockIdx.x * blockDim.x + threadIdx.x) >> 5);
    const int nwarps      = (int)((gridDim.x * blockDim.x) >> 5);

    const uint2* cfh = (const uint2*)g_cfh;   // row r -> cfh[r*4 + sub]

    int base = warp_global * 8;
    if (base >= n_pairs) return;

    // Prime the index pipeline
    int4 xi = __ldcg((const int4*)x + base + unit);
    int4 yi = __ldcg((const int4*)y + base + unit);

    while (base < n_pairs) {
        const int nbase = base + nwarps * 8;

        // ---- Issue all 8 row gathers back-to-back (MLP = 8) ----
        uint2 av0 = cfh[(size_t)(0 * NB_CAT + xi.x) * 4 + sub];
        uint2 bv0 = cfh[(size_t)(0 * NB_CAT + yi.x) * 4 + sub];
        uint2 av1 = cfh[(size_t)(1 * NB_CAT + xi.y) * 4 + sub];
        uint2 bv1 = cfh[(size_t)(1 * NB_CAT + yi.y) * 4 + sub];
        uint2 av2 = cfh[(size_t)(2 * NB_CAT + xi.z) * 4 + sub];
        uint2 bv2 = cfh[(size_t)(2 * NB_CAT + yi.z) * 4 + sub];
        uint2 av3 = cfh[(size_t)(3 * NB_CAT + xi.w) * 4 + sub];
        uint2 bv3 = cfh[(size_t)(3 * NB_CAT + yi.w) * 4 + sub];

        // ---- Diagonal term while gathers fly (fp32 std, exact) ----
        float acc = 0.0f;
        {
            const int xd = (sub == 0) ? xi.x : (sub == 1) ? xi.y : (sub == 2) ? xi.z : xi.w;
            const int yd = (sub == 0) ? yi.x : (sub == 1) ? yi.y : (sub == 2) ? yi.z : yi.w;
            if (xd == yd) {
                const float s = stdv[sub * NB_CAT + xd];
                acc = s * s;
            }
        }

        // ---- Prefetch next iteration's indices (hide DRAM latency) ----
        int4 nxi, nyi;
        if (nbase < n_pairs) {
            nxi = __ldcg((const int4*)x + nbase + unit);
            nyi = __ldcg((const int4*)y + nbase + unit);
        }
        xi = nxi;
        yi = nyi;

        // ---- Math: per-column dot in half2, fp32 cross-column accumulate ----
        {
            __half2 p0 = __hmul2(*(const __half2*)&av0.x, *(const __half2*)&bv0.x);
            p0 = __hfma2(*(const __half2*)&av0.y, *(const __half2*)&bv0.y, p0);
            __half2 p1 = __hmul2(*(const __half2*)&av1.x, *(const __half2*)&bv1.x);
            p1 = __hfma2(*(const __half2*)&av1.y, *(const __half2*)&bv1.y, p1);
            __half2 p2 = __hmul2(*(const __half2*)&av2.x, *(const __half2*)&bv2.x);
            p2 = __hfma2(*(const __half2*)&av2.y, *(const __half2*)&bv2.y, p2);
            __half2 p3 = __hmul2(*(const __half2*)&av3.x, *(const __half2*)&bv3.x);
            p3 = __hfma2(*(const __half2*)&av3.y, *(const __half2*)&bv3.y, p3);

            const float2 f0 = __half22float2(p0);
            const float2 f1 = __half22float2(p1);
            const float2 f2 = __half22float2(p2);
            const float2 f3 = __half22float2(p3);
            acc += (f0.x + f0.y) + (f1.x + f1.y);
            acc += (f2.x + f2.y) + (f3.x + f3.y);
        }

        // ---- Reduce over the 4 chunk lanes; lane 0 of each unit writes ----
        acc += __shfl_xor_sync(0xffffffffu, acc, 1);
        acc += __shfl_xor_sync(0xffffffffu, acc, 2);

        if (sub == 0) {
            out[base + unit] = acc;   // 8 lanes -> 32 contiguous bytes -> 1 wf
        }

        base = nbase;
    }
}

extern "C" void kernel_launch(void* const* d_in, const int* in_sizes, int n_in,
                              void* d_out, int out_size)
{
    const int*   x    = (const int*)d_in[0];
    const int*   y    = (const int*)d_in[1];
    const float* cf   = (const float*)d_in[2];
    const float* stdv = (const float*)d_in[3];
    float*       out  = (float*)d_out;

    const int n_pairs = out_size;  // 1048576

    // 1) Convert covar_factor fp32 -> fp16 (DRAM-streaming, ~1.5us)
    {
        const int n = N_COLS * NB_CAT * RANK / 2;
        convert_cf_kernel<<<(n + 255) / 256, 256>>>(cf);
    }

    // 2) Main gather kernel: single resident wave at 7 blocks/SM
    {
        const int threads = 256;
        const int blocks  = 148 * 7;
        pair_cov_kernel<<<blocks, threads>>>(x, y, stdv, out, n_pairs);
    }
}